// round 7
// baseline (speedup 1.0000x reference)
#include <cuda_runtime.h>
#include <math.h>

// Problem dims
#define S  64
#define H  1024
#define V  512
#define WV 300
#define NE 512

// Recurrent kernel config
#define RB  64   // blocks; each owns RC columns of ev
#define RC  16
#define RT  512

// Output offsets (reference return order)
#define OFF_ENTP 0
#define OFF_ACP  (S*NE)
#define OFF_ENT  (OFF_ACP + S*V)
#define OFF_ALL  (OFF_ENT + S*H)
#define OFF_ACT  (OFF_ALL + (size_t)S*NE*H)

// Scratch (device globals; no allocation allowed)
__device__ __align__(16) float g_HH[64*2048];     // dense [relu(h) | relu(hat)]
__device__ __align__(16) float g_ACd[64*512];     // dense sigmoid(ac)
__device__ __align__(16) float g_GP3[8*64*1024];  // w2v split-K partials
__device__ __align__(16) float g_W2V[S*H];
__device__ float g_CHOICE[S*2];
__device__ float g_SCAL[S];
// logit partials, entity-major transposed + double buffered: [buf][entity][p]
__device__ __align__(16) float g_PARTT[2*NE*64];
__device__ __align__(128) unsigned g_flags[RB*32]; // per-block barrier slot, 128B apart

// ---------------------------------------------------------------------------
// Dense split-N GEMM: Out[64,N] = act( X[64,K] @ W[N,K]^T + b )
// Block (0,0) also resets the 64 barrier flag slots (runs before k_recurrent).
// ---------------------------------------------------------------------------
__global__ void __launch_bounds__(256) gemm32(
    const float* __restrict__ X, int xstride,
    const float* __restrict__ Wa, const float* __restrict__ Wb, int NB,
    const float* __restrict__ bA, const float* __restrict__ bB,
    float* __restrict__ Out, int ostride, int K, int act)
{
    if (blockIdx.x == 0 && blockIdx.y == 0 && threadIdx.x < RB) {
        g_flags[threadIdx.x*32] = 0u;
    }
    __shared__ __align__(8) float Xs[32][34];
    __shared__ __align__(8) float Ws[32][34];
    int tid = threadIdx.x;
    int tx = tid & 15, ty = tid >> 4;
    int n0 = blockIdx.x * 32;
    int m0 = blockIdx.y * 32;

    float a00 = 0.f, a01 = 0.f, a10 = 0.f, a11 = 0.f;

    for (int kc = 0; kc < K; kc += 32) {
#pragma unroll
        for (int i = 0; i < 4; i++) {
            int e = tid + 256*i; int row = e >> 5, kk = e & 31;
            Xs[kk][row] = X[(size_t)(m0 + row)*xstride + kc + kk];
        }
#pragma unroll
        for (int i = 0; i < 4; i++) {
            int e = tid + 256*i; int nr = e >> 5, kk = e & 31;
            int n = n0 + nr;
            const float* Wp = (n < NB) ? (Wa + (size_t)n*K) : (Wb + (size_t)(n - NB)*K);
            Ws[kk][nr] = Wp[kc + kk];
        }
        __syncthreads();
#pragma unroll
        for (int kk = 0; kk < 32; kk++) {
            float x0 = Xs[kk][ty*2], x1 = Xs[kk][ty*2+1];
            float w0 = Ws[kk][tx*2], w1 = Ws[kk][tx*2+1];
            a00 += x0*w0; a01 += x0*w1;
            a10 += x1*w0; a11 += x1*w1;
        }
        __syncthreads();
    }

    int n = n0 + tx*2;
    float b0 = (n   < NB) ? bA[n]   : bB[n   - NB];
    float b1 = (n+1 < NB) ? bA[n+1] : bB[n+1 - NB];
    float r[2][2] = {{a00 + b0, a01 + b1}, {a10 + b0, a11 + b1}};
#pragma unroll
    for (int q = 0; q < 2; q++)
#pragma unroll
        for (int p = 0; p < 2; p++) {
            float v = r[q][p];
            if (act == 1)      v = fmaxf(v, 0.f);
            else if (act == 2) v = 1.f/(1.f + expf(-v));
            Out[(size_t)(m0 + ty*2 + q)*ostride + n0 + tx*2 + p] = v;
        }
}

// ---------------------------------------------------------------------------
// Split-K GEMM for w2v partials: GP3[ky][64][1024] = [relu(hat)|sig(ac)] @ W2w^T
// ---------------------------------------------------------------------------
__global__ void __launch_bounds__(256) gemm3(
    const float* __restrict__ W, float* __restrict__ OutP, int N, int K, int kslice)
{
    __shared__ __align__(16) float XsT[32][68];
    __shared__ __align__(16) float WsT[32][68];
    int tid = threadIdx.x;
    int tx = tid & 15, ty = tid >> 4;
    int n0 = blockIdx.x * 64;
    int kc0 = blockIdx.y * kslice;

    float acc[4][4];
#pragma unroll
    for (int r = 0; r < 4; r++)
#pragma unroll
        for (int q = 0; q < 4; q++) acc[r][q] = 0.f;

    for (int kc = kc0; kc < kc0 + kslice; kc += 32) {
#pragma unroll
        for (int i = 0; i < 8; i++) {
            int e = tid + 256*i; int row = e >> 5, kk = e & 31;
            int k = kc + kk;
            XsT[kk][row] = (k < 1024) ? g_HH[row*2048 + 1024 + k]
                                      : g_ACd[row*512 + (k - 1024)];
        }
#pragma unroll
        for (int i = 0; i < 8; i++) {
            int e = tid + 256*i; int nr = e >> 5, kk = e & 31;
            WsT[kk][nr] = W[(size_t)(n0 + nr)*K + kc + kk];
        }
        __syncthreads();
#pragma unroll
        for (int kk = 0; kk < 32; kk++) {
            float4 xa = *(const float4*)&XsT[kk][ty*4];
            float4 wb = *(const float4*)&WsT[kk][tx*4];
            acc[0][0] += xa.x*wb.x; acc[0][1] += xa.x*wb.y; acc[0][2] += xa.x*wb.z; acc[0][3] += xa.x*wb.w;
            acc[1][0] += xa.y*wb.x; acc[1][1] += xa.y*wb.y; acc[1][2] += xa.y*wb.z; acc[1][3] += xa.y*wb.w;
            acc[2][0] += xa.z*wb.x; acc[2][1] += xa.z*wb.y; acc[2][2] += xa.z*wb.z; acc[2][3] += xa.z*wb.w;
            acc[3][0] += xa.w*wb.x; acc[3][1] += xa.w*wb.y; acc[3][2] += xa.w*wb.z; acc[3][3] += xa.w*wb.w;
        }
        __syncthreads();
    }
    float* Po = OutP + (size_t)blockIdx.y*64*N + n0;
#pragma unroll
    for (int r = 0; r < 4; r++) {
        float4 v = make_float4(acc[r][0], acc[r][1], acc[r][2], acc[r][3]);
        *(float4*)&Po[(size_t)(ty*4 + r)*N + tx*4] = v;
    }
}

// ---------------------------------------------------------------------------
// Split flag barrier. arrive(): release-store generation into this block's
// slot (orders only the small partial stores issued before it). wait(): warp 0
// polls all 64 slots. Snapshot/output stores are issued BETWEEN arrive and
// wait so they are never in the release's ordered set.
// ---------------------------------------------------------------------------
__device__ __forceinline__ void bar_arrive(int tid, int blk, unsigned target)
{
    __syncthreads();
    if (tid == 0)
        asm volatile("st.release.gpu.global.u32 [%0], %1;"
                     :: "l"(&g_flags[blk*32]), "r"(target) : "memory");
}

__device__ __forceinline__ void bar_wait(int tid, unsigned target)
{
    if (tid < 32) {
        unsigned a, b;
        do {
            asm volatile("ld.acquire.gpu.global.u32 %0, [%1];"
                         : "=r"(a) : "l"(&g_flags[tid*32]) : "memory");
            asm volatile("ld.acquire.gpu.global.u32 %0, [%1];"
                         : "=r"(b) : "l"(&g_flags[(tid+32)*32]) : "memory");
        } while (!__all_sync(0xffffffffu, (a >= target) && (b >= target)));
    }
    __syncthreads();
}

// ---------------------------------------------------------------------------
// Persistent recurrent kernel (launch index 3; profiled).
// One grid barrier per step; all blocks redundantly finalize all 512 ents from
// the entity-major transposed partial buffer (16 LDG.128 per thread).
// ---------------------------------------------------------------------------
__global__ void __launch_bounds__(RT, 1) k_recurrent(
    const float* __restrict__ evin,
    const float* __restrict__ emb,
    const float* __restrict__ W2b,
    const float* __restrict__ W3w, const float* __restrict__ W3b,
    const float* __restrict__ W4w, const float* __restrict__ W4b,
    float* __restrict__ out)
{
    int tid = threadIdx.x;
    int blk = blockIdx.x;
    int c = tid & 15, s = tid >> 4;
    int j = blk*RC + c;
    int i0 = s*16;
    int lane = tid & 31, wid = tid >> 5;

    __shared__ float s_attn[NE];
    __shared__ float s_mat[NE*17];        // row-major padded transpose scratch
    __shared__ float s_part[32*17];
    __shared__ float s_kt[RC];
    __shared__ float s_red[16];
    __shared__ float s_sum;
    __shared__ float s_ac[V];
    __shared__ float s_bf[WV];
    __shared__ float s_cl[3];

    // issue ev load early (DRAM latency overlaps the smalls below)
    float evr[16];
#pragma unroll
    for (int r = 0; r < 16; r++) evr[r] = evin[(size_t)(i0 + r)*H + j];

    // ================= prologue: smalls for step t = blk =================
    {
        int t = blk;
        float a = g_ACd[t*V + tid];
        s_ac[tid] = a;
        out[OFF_ACP + t*V + tid] = a;
        float v = a;
#pragma unroll
        for (int o = 16; o; o >>= 1) v += __shfl_xor_sync(0xffffffffu, v, o);
        if (lane == 0) s_red[wid] = v;
        __syncthreads();
        if (tid < 16) {
            float x = s_red[tid];
#pragma unroll
            for (int o = 8; o; o >>= 1) x += __shfl_xor_sync(0x0000ffffu, x, o);
            if (tid == 0) s_sum = x;
        }
        __syncthreads();
        float acsum = s_sum;

        if (tid < WV) {
            float a0 = 0.f, a1 = 0.f, a2 = 0.f, a3 = 0.f;
            for (int i = 0; i < V; i += 4) {
                a0 += s_ac[i+0]*emb[(i+0)*WV + tid];
                a1 += s_ac[i+1]*emb[(i+1)*WV + tid];
                a2 += s_ac[i+2]*emb[(i+2)*WV + tid];
                a3 += s_ac[i+3]*emb[(i+3)*WV + tid];
            }
            float bf = ((a0+a1)+(a2+a3)) / acsum;
            s_bf[tid] = bf;
            out[OFF_ACT + t*WV + tid] = bf;
        }
        __syncthreads();

        float p = (tid < WV) ? s_bf[tid]*W4w[tid] : 0.f;
#pragma unroll
        for (int o = 16; o; o >>= 1) p += __shfl_xor_sync(0xffffffffu, p, o);
        if (lane == 0) s_red[wid] = p;
        __syncthreads();
        if (tid < 16) {
            float x = s_red[tid];
#pragma unroll
            for (int o = 8; o; o >>= 1) x += __shfl_xor_sync(0x0000ffffu, x, o);
            if (tid == 0) g_SCAL[t] = x + W4b[0];
        }

        if (wid < 3) {
            float a3v = 0.f;
            for (int k = lane; k < H; k += 32)
                a3v += g_HH[t*2048 + 1024 + k]*W3w[wid*H + k];
#pragma unroll
            for (int o = 16; o; o >>= 1) a3v += __shfl_xor_sync(0xffffffffu, a3v, o);
            if (lane == 0) s_cl[wid] = a3v + W3b[wid];
        }
        __syncthreads();
        if (tid == 0) {
            float m = fmaxf(s_cl[0], fmaxf(s_cl[1], s_cl[2]));
            float e0 = expf(s_cl[0]-m), e1 = expf(s_cl[1]-m), e2 = expf(s_cl[2]-m);
            float sm = e0 + e1 + e2;
            g_CHOICE[t*2+0] = e0/sm;
            g_CHOICE[t*2+1] = e1/sm;
        }

        // w2v[t] = W2b + sum_ky GP3[ky][t][:]
#pragma unroll
        for (int h2 = 0; h2 < 2; h2++) {
            int n = tid + 512*h2;
            float w = W2b[n];
#pragma unroll
            for (int ky = 0; ky < 8; ky++) w += g_GP3[ky*64*1024 + t*1024 + n];
            g_W2V[t*H + n] = w;
        }
    }
    bar_arrive(tid, blk, 1);
    bar_wait(tid, 1);

    // logit0 partials (buffer 0) via smem transpose -> PARTT[entity][blk]
    {
        float w = __ldcg(&g_W2V[j]);
#pragma unroll
        for (int r = 0; r < 16; r++) s_mat[(i0 + r)*17 + c] = evr[r]*w;
        __syncthreads();
        float p0 = 0.f, p1 = 0.f, p2 = 0.f, p3 = 0.f;
#pragma unroll
        for (int k = 0; k < 16; k += 4) {
            p0 += s_mat[tid*17 + k+0];
            p1 += s_mat[tid*17 + k+1];
            p2 += s_mat[tid*17 + k+2];
            p3 += s_mat[tid*17 + k+3];
        }
        g_PARTT[tid*64 + blk] = (p0+p1)+(p2+p3);
    }
    bar_arrive(tid, blk, 2);
    bar_wait(tid, 2);

    // ========================= 64 sequential steps =========================
    float prevE = 0.f;   // previous ent for entity tid
    for (int t = 0; t < S; t++) {
        float c0   = __ldcg(&g_CHOICE[t*2+0]);
        float c1   = __ldcg(&g_CHOICE[t*2+1]);
        float scal = __ldcg(&g_SCAL[t]);

        // gather entity tid's 64 partials (16 LDG.128, MLP 16)
        const float4* pt = (const float4*)(g_PARTT + (size_t)(t & 1)*NE*64 + tid*64);
        float q0 = 0.f, q1 = 0.f, q2 = 0.f, q3 = 0.f;
#pragma unroll
        for (int q = 0; q < 16; q += 4) {
            float4 v0 = __ldcg(pt + q+0);
            float4 v1 = __ldcg(pt + q+1);
            float4 v2 = __ldcg(pt + q+2);
            float4 v3 = __ldcg(pt + q+3);
            q0 += (v0.x + v0.y) + (v0.z + v0.w);
            q1 += (v1.x + v1.y) + (v1.z + v1.w);
            q2 += (v2.x + v2.y) + (v2.z + v2.w);
            q3 += (v3.x + v3.y) + (v3.z + v3.w);
        }
        float lg = (q0 + q1) + (q2 + q3);
        float ent = 1.f/(1.f + expf(-lg));
        float at = fmaf(c0, ent, c1*prevE);
        prevE = ent;
        s_attn[tid] = at;

        // asum = block reduction of attn
        float v = at;
#pragma unroll
        for (int o = 16; o; o >>= 1) v += __shfl_xor_sync(0xffffffffu, v, o);
        if (lane == 0) s_red[wid] = v;
        __syncthreads();
        if (tid < 16) {
            float x = s_red[tid];
#pragma unroll
            for (int o = 8; o; o >>= 1) x += __shfl_xor_sync(0x0000ffffu, x, o);
            if (tid == 0) s_sum = x;
        }
        __syncthreads();
        float asum = s_sum;

        // bar_et partial (register ev)
        float bacc = 0.f;
#pragma unroll
        for (int r = 0; r < 16; r++) bacc += s_attn[i0 + r]*evr[r];
        s_part[s*17 + c] = bacc;
        __syncthreads();
        if (tid < RC) {
            float b0 = 0.f, b1 = 0.f;
#pragma unroll
            for (int q = 0; q < 32; q += 2) {
                b0 += s_part[(q+0)*17 + tid];
                b1 += s_part[(q+1)*17 + tid];
            }
            float bar = (b0 + b1) / asum;
            out[OFF_ENT + t*H + blk*RC + tid] = bar;
            s_kt[tid] = fmaxf(scal*bar, 0.f);
        }
        __syncthreads();
        float kt = s_kt[c];

        if (t < S-1) {
            // update ev + next-step logit partials via smem transpose
            float w2vn = __ldcg(&g_W2V[(t+1)*H + j]);
#pragma unroll
            for (int r = 0; r < 16; r++) {
                float a  = s_attn[i0 + r];
                float nv = fmaf(a, kt - evr[r], evr[r]);
                evr[r] = nv;
                s_mat[(i0 + r)*17 + c] = nv*w2vn;
            }
            __syncthreads();
            float p0 = 0.f, p1 = 0.f, p2 = 0.f, p3 = 0.f;
#pragma unroll
            for (int k = 0; k < 16; k += 4) {
                p0 += s_mat[tid*17 + k+0];
                p1 += s_mat[tid*17 + k+1];
                p2 += s_mat[tid*17 + k+2];
                p3 += s_mat[tid*17 + k+3];
            }
            g_PARTT[(size_t)((t+1) & 1)*NE*64 + tid*64 + blk] = (p0+p1)+(p2+p3);

            // barrier arrival orders ONLY the partial store above; snapshot +
            // output writes issue after the release, draining off-path.
            bar_arrive(tid, blk, (unsigned)(3 + t));
            if (blk == 0) out[OFF_ENTP + t*NE + tid] = ent;
            {
                float* snap = out + OFF_ALL + (size_t)t*NE*H + j;
#pragma unroll
                for (int r = 0; r < 16; r++) __stcs(snap + (size_t)(i0 + r)*H, evr[r]);
            }
            bar_wait(tid, (unsigned)(3 + t));
        } else {
#pragma unroll
            for (int r = 0; r < 16; r++) {
                float a = s_attn[i0 + r];
                evr[r] = fmaf(a, kt - evr[r], evr[r]);
            }
            if (blk == 0) out[OFF_ENTP + t*NE + tid] = ent;
            float* snap = out + OFF_ALL + (size_t)t*NE*H + j;
#pragma unroll
            for (int r = 0; r < 16; r++) __stcs(snap + (size_t)(i0 + r)*H, evr[r]);
        }
    }
}

// ---------------------------------------------------------------------------
extern "C" void kernel_launch(void* const* d_in, const int* in_sizes, int n_in,
                              void* d_out, int out_size)
{
    (void)in_sizes; (void)n_in; (void)out_size;
    const float* vv  = (const float*)d_in[0];
    const float* ev  = (const float*)d_in[1];
    const float* A1w = (const float*)d_in[2];
    const float* A1b = (const float*)d_in[3];
    const float* A2w = (const float*)d_in[4];
    const float* A2b = (const float*)d_in[5];
    const float* emb = (const float*)d_in[6];
    const float* W1w = (const float*)d_in[7];
    const float* W1b = (const float*)d_in[8];
    const float* W2w = (const float*)d_in[9];
    const float* W2b = (const float*)d_in[10];
    const float* W3w = (const float*)d_in[11];
    const float* W3b = (const float*)d_in[12];
    const float* W4w = (const float*)d_in[13];
    const float* W4b = (const float*)d_in[14];
    float* out = (float*)d_out;

    float *pHH, *pAC, *pGP3;
    cudaGetSymbolAddress((void**)&pHH,  g_HH);
    cudaGetSymbolAddress((void**)&pAC,  g_ACd);
    cudaGetSymbolAddress((void**)&pGP3, g_GP3);

    // 0: [h|hat] = relu(vv @ [A1w|W1w]^T + bias)  (also resets barrier flags)
    gemm32<<<dim3(64, 2), 256>>>(vv, H, A1w, W1w, 1024, A1b, W1b, pHH, 2048, H, 1);
    // 1: ac = sigmoid(h @ A2w^T + A2b)
    gemm32<<<dim3(16, 2), 256>>>(pHH, 2048, A2w, A2w, 1<<30, A2b, A2b, pAC, 512, H, 2);
    // 2: w2v partials
    gemm3<<<dim3(16, 8), 256>>>(W2w, pGP3, 1024, 1536, 192);
    // 3: fused finish + recurrence
    k_recurrent<<<RB, RT>>>(ev, emb, W2b, W3w, W3b, W4w, W4b, out);
}

// round 8
// speedup vs baseline: 1.7611x; 1.7611x over previous
#include <cuda_runtime.h>
#include <math.h>

// Problem dims
#define S  64
#define H  1024
#define V  512
#define WV 300
#define NE 512

// Recurrent kernel config: 64 blocks x 512 threads.
// Thread patch: g = tid&3 -> cols [blk*16 + g*4, +4), s = tid>>2 -> rows [s*4, +4)
#define RB  64
#define RC  16
#define RT  512

// Output offsets (reference return order)
#define OFF_ENTP 0
#define OFF_ACP  (S*NE)
#define OFF_ENT  (OFF_ACP + S*V)
#define OFF_ALL  (OFF_ENT + S*H)
#define OFF_ACT  (OFF_ALL + (size_t)S*NE*H)

// Scratch (device globals; no allocation allowed)
__device__ __align__(16) float g_HH[64*2048];     // dense [relu(h) | relu(hat)]
__device__ __align__(16) float g_ACd[64*512];     // dense sigmoid(ac)
__device__ __align__(16) float g_GP3[8*64*1024];  // w2v split-K partials
__device__ __align__(16) float g_W2V[S*H];
__device__ float g_CHOICE[S*2];
__device__ float g_SCAL[S];
// logit partials, p-major (R4 layout), double buffered: [buf][p][entity]
__device__ __align__(16) float g_PART[2*RB*NE];
__device__ __align__(128) unsigned g_flags[RB*32]; // per-block barrier slot, 128B apart

// ---------------------------------------------------------------------------
// Dense split-N GEMM: Out[64,N] = act( X[64,K] @ W[N,K]^T + b )
// Block (0,0) also resets the 64 barrier flag slots (runs before k_recurrent).
// ---------------------------------------------------------------------------
__global__ void __launch_bounds__(256) gemm32(
    const float* __restrict__ X, int xstride,
    const float* __restrict__ Wa, const float* __restrict__ Wb, int NB,
    const float* __restrict__ bA, const float* __restrict__ bB,
    float* __restrict__ Out, int ostride, int K, int act)
{
    if (blockIdx.x == 0 && blockIdx.y == 0 && threadIdx.x < RB) {
        g_flags[threadIdx.x*32] = 0u;
    }
    __shared__ __align__(8) float Xs[32][34];
    __shared__ __align__(8) float Ws[32][34];
    int tid = threadIdx.x;
    int tx = tid & 15, ty = tid >> 4;
    int n0 = blockIdx.x * 32;
    int m0 = blockIdx.y * 32;

    float a00 = 0.f, a01 = 0.f, a10 = 0.f, a11 = 0.f;

    for (int kc = 0; kc < K; kc += 32) {
#pragma unroll
        for (int i = 0; i < 4; i++) {
            int e = tid + 256*i; int row = e >> 5, kk = e & 31;
            Xs[kk][row] = X[(size_t)(m0 + row)*xstride + kc + kk];
        }
#pragma unroll
        for (int i = 0; i < 4; i++) {
            int e = tid + 256*i; int nr = e >> 5, kk = e & 31;
            int n = n0 + nr;
            const float* Wp = (n < NB) ? (Wa + (size_t)n*K) : (Wb + (size_t)(n - NB)*K);
            Ws[kk][nr] = Wp[kc + kk];
        }
        __syncthreads();
#pragma unroll
        for (int kk = 0; kk < 32; kk++) {
            float x0 = Xs[kk][ty*2], x1 = Xs[kk][ty*2+1];
            float w0 = Ws[kk][tx*2], w1 = Ws[kk][tx*2+1];
            a00 += x0*w0; a01 += x0*w1;
            a10 += x1*w0; a11 += x1*w1;
        }
        __syncthreads();
    }

    int n = n0 + tx*2;
    float b0 = (n   < NB) ? bA[n]   : bB[n   - NB];
    float b1 = (n+1 < NB) ? bA[n+1] : bB[n+1 - NB];
    float r[2][2] = {{a00 + b0, a01 + b1}, {a10 + b0, a11 + b1}};
#pragma unroll
    for (int q = 0; q < 2; q++)
#pragma unroll
        for (int p = 0; p < 2; p++) {
            float v = r[q][p];
            if (act == 1)      v = fmaxf(v, 0.f);
            else if (act == 2) v = 1.f/(1.f + expf(-v));
            Out[(size_t)(m0 + ty*2 + q)*ostride + n0 + tx*2 + p] = v;
        }
}

// ---------------------------------------------------------------------------
// Split-K GEMM for w2v partials: GP3[ky][64][1024] = [relu(hat)|sig(ac)] @ W2w^T
// ---------------------------------------------------------------------------
__global__ void __launch_bounds__(256) gemm3(
    const float* __restrict__ W, float* __restrict__ OutP, int N, int K, int kslice)
{
    __shared__ __align__(16) float XsT[32][68];
    __shared__ __align__(16) float WsT[32][68];
    int tid = threadIdx.x;
    int tx = tid & 15, ty = tid >> 4;
    int n0 = blockIdx.x * 64;
    int kc0 = blockIdx.y * kslice;

    float acc[4][4];
#pragma unroll
    for (int r = 0; r < 4; r++)
#pragma unroll
        for (int q = 0; q < 4; q++) acc[r][q] = 0.f;

    for (int kc = kc0; kc < kc0 + kslice; kc += 32) {
#pragma unroll
        for (int i = 0; i < 8; i++) {
            int e = tid + 256*i; int row = e >> 5, kk = e & 31;
            int k = kc + kk;
            XsT[kk][row] = (k < 1024) ? g_HH[row*2048 + 1024 + k]
                                      : g_ACd[row*512 + (k - 1024)];
        }
#pragma unroll
        for (int i = 0; i < 8; i++) {
            int e = tid + 256*i; int nr = e >> 5, kk = e & 31;
            WsT[kk][nr] = W[(size_t)(n0 + nr)*K + kc + kk];
        }
        __syncthreads();
#pragma unroll
        for (int kk = 0; kk < 32; kk++) {
            float4 xa = *(const float4*)&XsT[kk][ty*4];
            float4 wb = *(const float4*)&WsT[kk][tx*4];
            acc[0][0] += xa.x*wb.x; acc[0][1] += xa.x*wb.y; acc[0][2] += xa.x*wb.z; acc[0][3] += xa.x*wb.w;
            acc[1][0] += xa.y*wb.x; acc[1][1] += xa.y*wb.y; acc[1][2] += xa.y*wb.z; acc[1][3] += xa.y*wb.w;
            acc[2][0] += xa.z*wb.x; acc[2][1] += xa.z*wb.y; acc[2][2] += xa.z*wb.z; acc[2][3] += xa.z*wb.w;
            acc[3][0] += xa.w*wb.x; acc[3][1] += xa.w*wb.y; acc[3][2] += xa.w*wb.z; acc[3][3] += xa.w*wb.w;
        }
        __syncthreads();
    }
    float* Po = OutP + (size_t)blockIdx.y*64*N + n0;
#pragma unroll
    for (int r = 0; r < 4; r++) {
        float4 v = make_float4(acc[r][0], acc[r][1], acc[r][2], acc[r][3]);
        *(float4*)&Po[(size_t)(ty*4 + r)*N + tx*4] = v;
    }
}

// ---------------------------------------------------------------------------
// Split flag barrier: arrive releases this block's slot; wait polls all 64.
// Bulky private-output stores are issued BETWEEN arrive and wait.
// ---------------------------------------------------------------------------
__device__ __forceinline__ void bar_arrive(int tid, int blk, unsigned target)
{
    __syncthreads();
    if (tid == 0)
        asm volatile("st.release.gpu.global.u32 [%0], %1;"
                     :: "l"(&g_flags[blk*32]), "r"(target) : "memory");
}

__device__ __forceinline__ void bar_wait(int tid, unsigned target)
{
    if (tid < 32) {
        unsigned a, b;
        do {
            asm volatile("ld.acquire.gpu.global.u32 %0, [%1];"
                         : "=r"(a) : "l"(&g_flags[tid*32]) : "memory");
            asm volatile("ld.acquire.gpu.global.u32 %0, [%1];"
                         : "=r"(b) : "l"(&g_flags[(tid+32)*32]) : "memory");
        } while (!__all_sync(0xffffffffu, (a >= target) && (b >= target)));
    }
    __syncthreads();
}

// ---------------------------------------------------------------------------
// Persistent recurrent kernel (launch index 3; profiled).
// ---------------------------------------------------------------------------
__global__ void __launch_bounds__(RT, 1) k_recurrent(
    const float* __restrict__ evin,
    const float* __restrict__ emb,
    const float* __restrict__ W2b,
    const float* __restrict__ W3w, const float* __restrict__ W3b,
    const float* __restrict__ W4w, const float* __restrict__ W4b,
    float* __restrict__ out)
{
    int tid = threadIdx.x;
    int blk = blockIdx.x;
    int g = tid & 3;          // col group (4 cols)
    int s = tid >> 2;         // row segment (4 rows), 0..127
    int jc = blk*RC + g*4;    // first col of this thread's group
    int i0 = s*4;             // first row
    int lane = tid & 31, wid = tid >> 5;

    __shared__ float s_attn[NE];
    __shared__ float s_pc[16][20];     // per-warp per-col bar_et partials (16B-aligned rows)
    __shared__ __align__(16) float s_kt[RC];
    __shared__ float s_red[16];
    __shared__ float s_sum;
    __shared__ float s_ac[V];
    __shared__ float s_bf[WV];
    __shared__ float s_cl[3];

    // ev patch in registers (issue early; overlaps prologue)
    float4 evr[4];
#pragma unroll
    for (int r = 0; r < 4; r++)
        evr[r] = *(const float4*)(evin + (size_t)(i0 + r)*H + jc);

    // ================= prologue: smalls for step t = blk =================
    {
        int t = blk;
        float a = g_ACd[t*V + tid];
        s_ac[tid] = a;
        out[OFF_ACP + t*V + tid] = a;
        float v = a;
#pragma unroll
        for (int o = 16; o; o >>= 1) v += __shfl_xor_sync(0xffffffffu, v, o);
        if (lane == 0) s_red[wid] = v;
        __syncthreads();
        if (tid < 16) {
            float x = s_red[tid];
#pragma unroll
            for (int o = 8; o; o >>= 1) x += __shfl_xor_sync(0x0000ffffu, x, o);
            if (tid == 0) s_sum = x;
        }
        __syncthreads();
        float acsum = s_sum;

        if (tid < WV) {
            float a0 = 0.f, a1 = 0.f, a2 = 0.f, a3 = 0.f;
            for (int i = 0; i < V; i += 4) {
                a0 += s_ac[i+0]*emb[(i+0)*WV + tid];
                a1 += s_ac[i+1]*emb[(i+1)*WV + tid];
                a2 += s_ac[i+2]*emb[(i+2)*WV + tid];
                a3 += s_ac[i+3]*emb[(i+3)*WV + tid];
            }
            float bf = ((a0+a1)+(a2+a3)) / acsum;
            s_bf[tid] = bf;
            out[OFF_ACT + t*WV + tid] = bf;
        }
        __syncthreads();

        float p = (tid < WV) ? s_bf[tid]*W4w[tid] : 0.f;
#pragma unroll
        for (int o = 16; o; o >>= 1) p += __shfl_xor_sync(0xffffffffu, p, o);
        if (lane == 0) s_red[wid] = p;
        __syncthreads();
        if (tid < 16) {
            float x = s_red[tid];
#pragma unroll
            for (int o = 8; o; o >>= 1) x += __shfl_xor_sync(0x0000ffffu, x, o);
            if (tid == 0) g_SCAL[t] = x + W4b[0];
        }

        if (wid < 3) {
            float a3v = 0.f;
            for (int k = lane; k < H; k += 32)
                a3v += g_HH[t*2048 + 1024 + k]*W3w[wid*H + k];
#pragma unroll
            for (int o = 16; o; o >>= 1) a3v += __shfl_xor_sync(0xffffffffu, a3v, o);
            if (lane == 0) s_cl[wid] = a3v + W3b[wid];
        }
        __syncthreads();
        if (tid == 0) {
            float m = fmaxf(s_cl[0], fmaxf(s_cl[1], s_cl[2]));
            float e0 = expf(s_cl[0]-m), e1 = expf(s_cl[1]-m), e2 = expf(s_cl[2]-m);
            float sm = e0 + e1 + e2;
            g_CHOICE[t*2+0] = e0/sm;
            g_CHOICE[t*2+1] = e1/sm;
        }

        // w2v[t] = W2b + sum_ky GP3[ky][t][:]
#pragma unroll
        for (int h2 = 0; h2 < 2; h2++) {
            int n = tid + 512*h2;
            float w = W2b[n];
#pragma unroll
            for (int ky = 0; ky < 8; ky++) w += g_GP3[ky*64*1024 + t*1024 + n];
            g_W2V[t*H + n] = w;
        }
    }
    bar_arrive(tid, blk, 1);
    bar_wait(tid, 1);

    // logit0 partials -> p-major g_PART[0][blk][*], via 2 shfls + STG.128
    {
        float4 w4 = __ldcg((const float4*)(g_W2V + jc));
        float lp[4];
#pragma unroll
        for (int r = 0; r < 4; r++)
            lp[r] = evr[r].x*w4.x + evr[r].y*w4.y + evr[r].z*w4.z + evr[r].w*w4.w;
#pragma unroll
        for (int r = 0; r < 4; r++) {
            lp[r] += __shfl_xor_sync(0xffffffffu, lp[r], 1);
            lp[r] += __shfl_xor_sync(0xffffffffu, lp[r], 2);
        }
        if (g == 0)
            *(float4*)(g_PART + blk*NE + i0) = make_float4(lp[0], lp[1], lp[2], lp[3]);
    }
    bar_arrive(tid, blk, 2);
    bar_wait(tid, 2);

    // ========================= 64 sequential steps =========================
    float prevE = 0.f;   // previous ent for entity tid
    for (int t = 0; t < S; t++) {
        float c0   = __ldcg(&g_CHOICE[t*2+0]);
        float c1   = __ldcg(&g_CHOICE[t*2+1]);
        float scal = __ldcg(&g_SCAL[t]);

        // gather entity tid's 64 partials, p-major (coalesced: 1 line/warp/p)
        const float* pp = g_PART + (size_t)(t & 1)*RB*NE + tid;
        float q0 = 0.f, q1 = 0.f, q2 = 0.f, q3 = 0.f;
#pragma unroll
        for (int bb = 0; bb < RB; bb += 4) {
            q0 += __ldcg(pp + (bb+0)*NE);
            q1 += __ldcg(pp + (bb+1)*NE);
            q2 += __ldcg(pp + (bb+2)*NE);
            q3 += __ldcg(pp + (bb+3)*NE);
        }
        float lg = (q0 + q1) + (q2 + q3);
        float ent = 1.f/(1.f + expf(-lg));
        float at = fmaf(c0, ent, c1*prevE);
        prevE = ent;
        s_attn[tid] = at;

        // asum = block reduction of attn
        float v = at;
#pragma unroll
        for (int o = 16; o; o >>= 1) v += __shfl_xor_sync(0xffffffffu, v, o);
        if (lane == 0) s_red[wid] = v;
        __syncthreads();
        if (tid < 16) {
            float x = s_red[tid];
#pragma unroll
            for (int o = 8; o; o >>= 1) x += __shfl_xor_sync(0x0000ffffu, x, o);
            if (tid == 0) s_sum = x;
        }
        __syncthreads();
        float asum = s_sum;

        // bar_et partial: per-thread float4 over 4 rows, reduce s within warp
        float4 bacc = make_float4(0.f, 0.f, 0.f, 0.f);
#pragma unroll
        for (int r = 0; r < 4; r++) {
            float a = s_attn[i0 + r];
            bacc.x = fmaf(a, evr[r].x, bacc.x);
            bacc.y = fmaf(a, evr[r].y, bacc.y);
            bacc.z = fmaf(a, evr[r].z, bacc.z);
            bacc.w = fmaf(a, evr[r].w, bacc.w);
        }
#pragma unroll
        for (int o = 4; o <= 16; o <<= 1) {
            bacc.x += __shfl_xor_sync(0xffffffffu, bacc.x, o);
            bacc.y += __shfl_xor_sync(0xffffffffu, bacc.y, o);
            bacc.z += __shfl_xor_sync(0xffffffffu, bacc.z, o);
            bacc.w += __shfl_xor_sync(0xffffffffu, bacc.w, o);
        }
        if (lane < 4) *(float4*)&s_pc[wid][lane*4] = bacc;
        __syncthreads();
        if (tid < RC) {
            float bs = 0.f;
#pragma unroll
            for (int w = 0; w < 16; w++) bs += s_pc[w][tid];
            float bar = bs / asum;
            out[OFF_ENT + t*H + blk*RC + tid] = bar;
            s_kt[tid] = fmaxf(scal*bar, 0.f);
        }
        __syncthreads();
        float4 kt4 = *(const float4*)&s_kt[g*4];

        if (t < S-1) {
            // update ev + next-step logit partials (2 shfls, STG.128)
            float4 w4 = __ldcg((const float4*)(g_W2V + (t+1)*H + jc));
            float lp[4];
#pragma unroll
            for (int r = 0; r < 4; r++) {
                float a = s_attn[i0 + r];
                evr[r].x = fmaf(a, kt4.x - evr[r].x, evr[r].x);
                evr[r].y = fmaf(a, kt4.y - evr[r].y, evr[r].y);
                evr[r].z = fmaf(a, kt4.z - evr[r].z, evr[r].z);
                evr[r].w = fmaf(a, kt4.w - evr[r].w, evr[r].w);
                lp[r] = evr[r].x*w4.x + evr[r].y*w4.y + evr[r].z*w4.z + evr[r].w*w4.w;
            }
#pragma unroll
            for (int r = 0; r < 4; r++) {
                lp[r] += __shfl_xor_sync(0xffffffffu, lp[r], 1);
                lp[r] += __shfl_xor_sync(0xffffffffu, lp[r], 2);
            }
            if (g == 0)
                *(float4*)(g_PART + (size_t)((t+1) & 1)*RB*NE + blk*NE + i0)
                    = make_float4(lp[0], lp[1], lp[2], lp[3]);

            // arrive orders only the partial store; snapshot drains off-path
            bar_arrive(tid, blk, (unsigned)(3 + t));
            if (blk == 0) out[OFF_ENTP + t*NE + tid] = ent;
            {
                float* snap = out + OFF_ALL + (size_t)t*NE*H + jc;
#pragma unroll
                for (int r = 0; r < 4; r++)
                    __stcs((float4*)(snap + (size_t)(i0 + r)*H), evr[r]);
            }
            bar_wait(tid, (unsigned)(3 + t));
        } else {
#pragma unroll
            for (int r = 0; r < 4; r++) {
                float a = s_attn[i0 + r];
                evr[r].x = fmaf(a, kt4.x - evr[r].x, evr[r].x);
                evr[r].y = fmaf(a, kt4.y - evr[r].y, evr[r].y);
                evr[r].z = fmaf(a, kt4.z - evr[r].z, evr[r].z);
                evr[r].w = fmaf(a, kt4.w - evr[r].w, evr[r].w);
            }
            if (blk == 0) out[OFF_ENTP + t*NE + tid] = ent;
            float* snap = out + OFF_ALL + (size_t)t*NE*H + jc;
#pragma unroll
            for (int r = 0; r < 4; r++)
                __stcs((float4*)(snap + (size_t)(i0 + r)*H), evr[r]);
        }
    }
}

// ---------------------------------------------------------------------------
extern "C" void kernel_launch(void* const* d_in, const int* in_sizes, int n_in,
                              void* d_out, int out_size)
{
    (void)in_sizes; (void)n_in; (void)out_size;
    const float* vv  = (const float*)d_in[0];
    const float* ev  = (const float*)d_in[1];
    const float* A1w = (const float*)d_in[2];
    const float* A1b = (const float*)d_in[3];
    const float* A2w = (const float*)d_in[4];
    const float* A2b = (const float*)d_in[5];
    const float* emb = (const float*)d_in[6];
    const float* W1w = (const float*)d_in[7];
    const float* W1b = (const float*)d_in[8];
    const float* W2w = (const float*)d_in[9];
    const float* W2b = (const float*)d_in[10];
    const float* W3w = (const float*)d_in[11];
    const float* W3b = (const float*)d_in[12];
    const float* W4w = (const float*)d_in[13];
    const float* W4b = (const float*)d_in[14];
    float* out = (float*)d_out;

    float *pHH, *pAC, *pGP3;
    cudaGetSymbolAddress((void**)&pHH,  g_HH);
    cudaGetSymbolAddress((void**)&pAC,  g_ACd);
    cudaGetSymbolAddress((void**)&pGP3, g_GP3);

    // 0: [h|hat] = relu(vv @ [A1w|W1w]^T + bias)  (also resets barrier flags)
    gemm32<<<dim3(64, 2), 256>>>(vv, H, A1w, W1w, 1024, A1b, W1b, pHH, 2048, H, 1);
    // 1: ac = sigmoid(h @ A2w^T + A2b)
    gemm32<<<dim3(16, 2), 256>>>(pHH, 2048, A2w, A2w, 1<<30, A2b, A2b, pAC, 512, H, 2);
    // 2: w2v partials
    gemm3<<<dim3(16, 8), 256>>>(W2w, pGP3, 1024, 1536, 192);
    // 3: fused finish + recurrence
    k_recurrent<<<RB, RT>>>(ev, emb, W2b, W3w, W3b, W4w, W4b, out);
}